// round 16
// baseline (speedup 1.0000x reference)
#include <cuda_runtime.h>
#include <cuda_fp16.h>
#include <cstdint>

#define NN 524288   // nodes
#define DD 256      // input dim
#define HH 128      // hidden dim
#define BB 2048     // segments

// ---------------- scratch (device globals; no allocation allowed) ----------
__device__ float    g_scores[NN];
__device__ uint32_t g_w1ph[(DD / 2) * HH];  // permuted half2 W1

// ---------------- helpers ---------------------------------------------------
__device__ __forceinline__ float tanha(float x) {
    float y;
    asm("tanh.approx.f32 %0, %1;" : "=f"(y) : "f"(x));
    return y;
}
__device__ __forceinline__ uint32_t smem_u32(const void* p) {
    uint32_t a;
    asm("{ .reg .u64 t; cvta.to.shared.u64 t, %1; cvt.u32.u64 %0, t; }" : "=r"(a) : "l"(p));
    return a;
}
__device__ __forceinline__ uint32_t pack_h2(float lo, float hi) {
    __half2 h = __floats2half2_rn(lo, hi);
    return *(uint32_t*)&h;
}
#define CP16(dst, src)  asm volatile("cp.async.ca.shared.global [%0], [%1], 16;" :: "r"(dst), "l"(src) : "memory")
#define CP_COMMIT()     asm volatile("cp.async.commit_group;" ::: "memory")
#define CP_WAIT(n)      asm volatile("cp.async.wait_group %0;" :: "n"(n) : "memory")

__device__ __forceinline__ void mma_f16(float& c0, float& c1, float& c2, float& c3,
                                        uint32_t a0, uint32_t a1, uint32_t a2, uint32_t a3,
                                        uint32_t b0, uint32_t b1) {
    asm("mma.sync.aligned.m16n8k16.row.col.f32.f16.f16.f32 "
        "{%0,%1,%2,%3}, {%4,%5,%6,%7}, {%8,%9}, {%0,%1,%2,%3};"
        : "+f"(c0), "+f"(c1), "+f"(c2), "+f"(c3)
        : "r"(a0), "r"(a1), "r"(a2), "r"(a3), "r"(b0), "r"(b1));
}

__device__ __forceinline__ void ldsm_x4(uint32_t& r0, uint32_t& r1, uint32_t& r2, uint32_t& r3,
                                        uint32_t addr) {
    asm volatile("ldmatrix.sync.aligned.m8n8.x4.shared.b16 {%0,%1,%2,%3}, [%4];"
                 : "=r"(r0), "=r"(r1), "=r"(r2), "=r"(r3) : "r"(addr));
}

// ---------------- kernel 0: W1 -> permuted packed half2 (one-shot) ---------
__global__ void w1h_kernel(const float* __restrict__ W1) {
    int k2 = blockIdx.x;         // 0..127
    int c  = threadIdx.x;        // 0..127
    g_w1ph[k2 * HH + (c & 7) * 16 + (c >> 3)] =
        pack_h2(W1[(2 * k2) * HH + c], W1[(2 * k2 + 1) * HH + c]);
}

// ---------------- kernel A: scores = tanh(x@W1 + b1) @ W2 + b2 -------------
// fp16 m16n8k16, ldmatrix A-frags, cp.async W1. 256 threads, 2 CTAs/SM.
// CTA tile: 128 nodes x 128 cols. Warp tile: 32 nodes x 64 cols.
// ONE barrier per k-chunk: x double-buffered, W1 TRIPLE-buffered so the
// cp.async issued one-ahead never collides with the chunk still being read.
#define KC 32
#define K2C 16
#define XS_STRIDE  20
#define W1P_STRIDE 132
#define XBUF_B  (128 * XS_STRIDE * 4)   // 10240 B
#define W1BUF_B (K2C * W1P_STRIDE * 4)  // 8448 B
#define OFF_X    0
#define OFF_W1   (2 * XBUF_B)            // 20480
#define OFF_B1   (OFF_W1 + 3 * W1BUF_B)  // 45824
#define OFF_W2   (OFF_B1 + 512)
#define OFF_PART (OFF_W2 + 512)
#define OFF_B2   (OFF_PART + 512)
#define SMEM_A_BYTES (OFF_B2 + 16)       // ~47.4 KB (2 CTAs -> ~94.7 KB/SM)

__global__ void __launch_bounds__(256, 2)
scores_kernel(const float* __restrict__ x,
              const float* __restrict__ b1,
              const float* __restrict__ W2,
              const float* __restrict__ b2) {
    extern __shared__ char smem[];
    const uint32_t sb = smem_u32(smem);

    float* b1s  = (float*)(smem + OFF_B1);
    float* w2s  = (float*)(smem + OFF_W2);
    float* part = (float*)(smem + OFF_PART);

    const int tid  = threadIdx.x;
    const int lane = tid & 31;
    const int wid  = tid >> 5;
    const int t    = lane & 3;          // k2 row within group
    const int g    = lane >> 2;         // group id
    const int wn   = (wid & 3) * 32;    // warp node base
    const int chf  = wid >> 2;          // column half
    const int n0   = blockIdx.x * 128;

    if (tid < 128) { b1s[tid] = b1[tid]; w2s[tid] = W2[tid]; }
    if (tid == 0)  { ((float*)(smem + OFF_B2))[0] = b2[0]; }

    float acc[2][8][4];
    #pragma unroll
    for (int ra = 0; ra < 2; ++ra)
        #pragma unroll
        for (int j = 0; j < 8; ++j)
            #pragma unroll
            for (int r = 0; r < 4; ++r) acc[ra][j][r] = 0.0f;

    const float4* x4   = (const float4*)x;
    const char*   wsrc = (const char*)g_w1ph;

    // staging decompositions
    const int xnode = tid >> 1, xjj = tid & 1;  // x: node, j' = xjj + 2i
    const int wrow  = tid >> 5, wq  = tid & 31; // W1: +tt*8 k2-rows, 16B group

    // ldmatrix per-lane address pieces
    const uint32_t lm_row  = (uint32_t)(wn + (lane & 15)) * (XS_STRIDE * 4)
                           + (uint32_t)(lane >> 4) * 16;

    // ---- prologue: cp.async W1 chunk 0 into wbuf 0; LDG x chunk 0 ----
    #pragma unroll
    for (int tt = 0; tt < 2; ++tt) {
        int row = wrow + tt * 8;
        CP16(sb + OFF_W1 + (uint32_t)(row * W1P_STRIDE + 4 * wq) * 4,
             wsrc + (size_t)(row * HH + 4 * wq) * 4);
    }
    CP_COMMIT();

    float4 rx[4];
    #pragma unroll
    for (int i = 0; i < 2; ++i) {
        int jp = xjj + 2 * i;
        rx[2 * i]     = x4[(size_t)(n0 + xnode) * 64 + 2 * jp];
        rx[2 * i + 1] = x4[(size_t)(n0 + xnode) * 64 + 2 * jp + 1];
    }

    #pragma unroll
    for (int ch = 0; ch < 8; ++ch) {
        const int xbuf = ch & 1;
        const int wbuf = ch % 3;
        uint32_t* xb  = (uint32_t*)(smem + OFF_X  + xbuf * XBUF_B);
        uint32_t* w1b = (uint32_t*)(smem + OFF_W1 + wbuf * W1BUF_B);
        const uint32_t xb_u32 = sb + OFF_X + xbuf * XBUF_B;

        // ---- store staged x chunk (cvt to half2, STS.128) ----
        #pragma unroll
        for (int i = 0; i < 2; ++i) {
            int jp = xjj + 2 * i;
            float4 f0 = rx[2 * i], f1 = rx[2 * i + 1];
            uint4 u;
            u.x = pack_h2(f0.x, f0.y); u.y = pack_h2(f0.z, f0.w);
            u.z = pack_h2(f1.x, f1.y); u.w = pack_h2(f1.z, f1.w);
            *(uint4*)(xb + xnode * XS_STRIDE + 4 * jp) = u;
        }

        // ---- issue next chunk's loads (W1 -> wbuf (ch+1)%3: no collision
        //      with compute(ch-1) on (ch-1)%3 or compute(ch) on ch%3) ----
        if (ch < 7) {
            const uint32_t wo = OFF_W1 + ((ch + 1) % 3) * W1BUF_B;
            #pragma unroll
            for (int tt = 0; tt < 2; ++tt) {
                int row = wrow + tt * 8;
                CP16(sb + wo + (uint32_t)(row * W1P_STRIDE + 4 * wq) * 4,
                     wsrc + (size_t)(((ch + 1) * K2C + row) * HH + 4 * wq) * 4);
            }
            CP_COMMIT();
            #pragma unroll
            for (int i = 0; i < 2; ++i) {
                int jp = xjj + 2 * i;
                rx[2 * i]     = x4[(size_t)(n0 + xnode) * 64 + (ch + 1) * 8 + 2 * jp];
                rx[2 * i + 1] = x4[(size_t)(n0 + xnode) * 64 + (ch + 1) * 8 + 2 * jp + 1];
            }
            CP_WAIT(1);   // chunk ch's W1 complete; ch+1 in flight
        } else {
            CP_WAIT(0);
        }
        __syncthreads();   // single barrier per chunk

        // ---- compute 2 k-steps (K=16 each) ----
        #pragma unroll
        for (int ks = 0; ks < 2; ++ks) {
            const int k2l = ks * 8;
            uint32_t ax[2][4];
            #pragma unroll
            for (int ra = 0; ra < 2; ++ra) {
                uint32_t addr = xb_u32 + lm_row
                              + (uint32_t)(16 * ra) * (XS_STRIDE * 4)
                              + (uint32_t)(k2l * 4);
                ldsm_x4(ax[ra][0], ax[ra][1], ax[ra][2], ax[ra][3], addr);
            }
            const uint32_t* r0 = w1b + (k2l + t) * W1P_STRIDE + g * 16 + chf * 8;
            const uint32_t* r1 = r0 + 4 * W1P_STRIDE;
            uint4 u0 = *(const uint4*)(r0);
            uint4 u1 = *(const uint4*)(r0 + 4);
            uint4 v0 = *(const uint4*)(r1);
            uint4 v1 = *(const uint4*)(r1 + 4);
            uint32_t bu[8] = {u0.x, u0.y, u0.z, u0.w, u1.x, u1.y, u1.z, u1.w};
            uint32_t bv[8] = {v0.x, v0.y, v0.z, v0.w, v1.x, v1.y, v1.z, v1.w};

            #pragma unroll
            for (int ra = 0; ra < 2; ++ra) {
                #pragma unroll
                for (int j = 0; j < 8; ++j) {
                    mma_f16(acc[ra][j][0], acc[ra][j][1], acc[ra][j][2], acc[ra][j][3],
                            ax[ra][0], ax[ra][1], ax[ra][2], ax[ra][3],
                            bu[j], bv[j]);
                }
            }
        }
        // no trailing barrier: W1 triple-buffer + x double-buffer make the
        // one-ahead cp.async / STS safe (see hazard analysis in header).
    }

    // ---- epilogue: +b1, tanh, dot W2, reduce over t, combine col halves ----
    float p[4] = {0.f, 0.f, 0.f, 0.f};
    #pragma unroll
    for (int ra = 0; ra < 2; ++ra) {
        #pragma unroll
        for (int j = 0; j < 8; ++j) {
            #pragma unroll
            for (int rr = 0; rr < 2; ++rr) {
                int cc = (chf * 8 + j) * 8 + 2 * t + rr;
                float bb = b1s[cc], ww = w2s[cc];
                p[2 * ra]     += tanha(acc[ra][j][rr]     + bb) * ww;
                p[2 * ra + 1] += tanha(acc[ra][j][2 + rr] + bb) * ww;
            }
        }
    }
    #pragma unroll
    for (int i = 0; i < 4; ++i) {
        p[i] += __shfl_xor_sync(0xffffffffu, p[i], 1);
        p[i] += __shfl_xor_sync(0xffffffffu, p[i], 2);
    }
    __syncthreads();   // all compute done before part[] exchange
    if (t == 0 && chf == 0) {
        part[wn + g]      = p[0];
        part[wn + g + 8]  = p[1];
        part[wn + g + 16] = p[2];
        part[wn + g + 24] = p[3];
    }
    __syncthreads();
    if (t == 0 && chf == 1) {
        float bb2 = ((float*)(smem + OFF_B2))[0];
        g_scores[n0 + wn + g]      = part[wn + g]      + p[0] + bb2;
        g_scores[n0 + wn + g + 8]  = part[wn + g + 8]  + p[1] + bb2;
        g_scores[n0 + wn + g + 16] = part[wn + g + 16] + p[2] + bb2;
        g_scores[n0 + wn + g + 24] = part[wn + g + 24] + p[3] + bb2;
    }
}

// ---------------- binary search ---------------------------------------------
__device__ __forceinline__ int lower_bound_i32(const int* __restrict__ a, int n, int v) {
    int lo = 0, hi = n;
    while (lo < hi) {
        int mid = (lo + hi) >> 1;
        if (a[mid] < v) lo = mid + 1; else hi = mid;
    }
    return lo;
}

// ---------------- kernel C: fused softmax + pooling (2 passes, R15) ---------
__global__ void pool_kernel(const float* __restrict__ x,
                            const int* __restrict__ batch,
                            float* __restrict__ out) {
    const int b = blockIdx.x;
    const int tid = threadIdx.x;   // dim d
    __shared__ int se[2];
    __shared__ float red[256];
    __shared__ float ws[256];

    if (tid == 0) {
        se[0] = lower_bound_i32(batch, NN, b);
        se[1] = lower_bound_i32(batch, NN, b + 1);
    }
    __syncthreads();
    const int st = se[0], en = se[1];

    // pass 1: Z = sum of unshifted exp (scores bounded, f32-safe)
    float z = 0.0f;
    for (int i = st + tid; i < en; i += 256) z += expf(g_scores[i]);
    red[tid] = z;
    __syncthreads();
    #pragma unroll
    for (int off = 128; off > 0; off >>= 1) {
        if (tid < off) red[tid] += red[tid + off];
        __syncthreads();
    }
    const float Z = red[0];
    const float invZ = (en > st && Z > 0.0f) ? (1.0f / Z) : 0.0f;
    __syncthreads();

    // pass 2: weighted pooling
    float acc = 0.0f;
    for (int i0 = st; i0 < en; i0 += 256) {
        int cnt = min(256, en - i0);
        __syncthreads();
        if (tid < cnt) ws[tid] = expf(g_scores[i0 + tid]) * invZ;
        __syncthreads();
        const float* xp = x + (size_t)i0 * DD + tid;
        int j = 0;
        for (; j + 8 <= cnt; j += 8) {
            float v0 = xp[(size_t)(j + 0) * DD];
            float v1 = xp[(size_t)(j + 1) * DD];
            float v2 = xp[(size_t)(j + 2) * DD];
            float v3 = xp[(size_t)(j + 3) * DD];
            float v4 = xp[(size_t)(j + 4) * DD];
            float v5 = xp[(size_t)(j + 5) * DD];
            float v6 = xp[(size_t)(j + 6) * DD];
            float v7 = xp[(size_t)(j + 7) * DD];
            acc += v0 * ws[j + 0]; acc += v1 * ws[j + 1];
            acc += v2 * ws[j + 2]; acc += v3 * ws[j + 3];
            acc += v4 * ws[j + 4]; acc += v5 * ws[j + 5];
            acc += v6 * ws[j + 6]; acc += v7 * ws[j + 7];
        }
        for (; j < cnt; ++j) acc += xp[(size_t)j * DD] * ws[j];
    }
    out[(size_t)b * DD + tid] = acc;
}

// ---------------- launch ------------------------------------------------------
extern "C" void kernel_launch(void* const* d_in, const int* in_sizes, int n_in,
                              void* d_out, int out_size) {
    (void)in_sizes; (void)n_in; (void)out_size;
    const float* x     = (const float*)d_in[0];
    const int*   batch = (const int*)d_in[1];
    const float* W1    = (const float*)d_in[2];
    const float* b1    = (const float*)d_in[3];
    const float* W2    = (const float*)d_in[4];
    const float* b2    = (const float*)d_in[5];
    float*       out   = (float*)d_out;

    cudaFuncSetAttribute(scores_kernel,
                         cudaFuncAttributeMaxDynamicSharedMemorySize,
                         SMEM_A_BYTES);

    w1h_kernel<<<DD / 2, HH>>>(W1);
    scores_kernel<<<NN / 128, 256, SMEM_A_BYTES>>>(x, b1, W2, b2);
    pool_kernel<<<BB, 256>>>(x, batch, out);
}